// round 1
// baseline (speedup 1.0000x reference)
#include <cuda_runtime.h>
#include <cstdint>
#include <cstddef>

#define N_SIMP 8192
#define KF 8
#define BATCH 64
#define FEAT 128

// ---- kernel 1 tiling: wL = W @ L ----
#define SEG1 32                    // row segments
#define ROWS1 (N_SIMP / SEG1)      // 256 rows per segment
#define COLB1 16                   // column blocks
#define COLS1 (N_SIMP / COLB1)     // 512 cols per block = 128 thr * 4

// ---- kernel 2 tiling: out = wL @ x[b] ----
#define SEG2 8                     // n segments
#define ROWS2 (N_SIMP / SEG2)      // 1024 n per segment
#define PART2 (SEG2 * 4)           // 32 partials (4 n-subgroups per block)

typedef unsigned long long ull;

// Scratch (device globals: allocation-free rule)
__device__ float g_wL_part[SEG1][KF][N_SIMP];          // 8 MB
__device__ float g_wL[KF][N_SIMP];                     // 256 KB
__device__ float g_acc_part[PART2][KF][BATCH][FEAT];   // 8 MB

__device__ __forceinline__ ull pack_dup(float a) {
    ull r; asm("mov.b64 %0, {%1, %1};" : "=l"(r) : "f"(a)); return r;
}
__device__ __forceinline__ void fma2(ull& d, ull a, ull b) {
    // packed f32x2 FMA: d = a*b + d on both halves (FFMA2 in SASS)
    asm("fma.rn.f32x2 %0, %1, %2, %0;" : "+l"(d) : "l"(a), "l"(b));
}
__device__ __forceinline__ float2 unpack2(ull v) {
    float2 r; asm("mov.b64 {%0, %1}, %2;" : "=f"(r.x), "=f"(r.y) : "l"(v)); return r;
}

// ============================================================
// k1: partial wL. Block = (col block, row segment).
// Thread owns 4 contiguous L columns, all 8 filters (as 4 k-pairs).
// ============================================================
__global__ __launch_bounds__(128) void k1_wl(const float* __restrict__ W,
                                             const float* __restrict__ L) {
    const int tid  = threadIdx.x;
    const int colb = blockIdx.x;
    const int seg  = blockIdx.y;
    const int c0   = colb * COLS1 + tid * 4;
    const int m0   = seg * ROWS1;

    // W segment staged as k-pairs: wtp[kp][m] = {W[2kp][m0+m], W[2kp+1][m0+m]}
    __shared__ float2 wtp[4][ROWS1];   // 8 KB
    for (int idx = tid; idx < 4 * ROWS1; idx += 128) {
        int kp = idx / ROWS1;
        int m  = idx % ROWS1;
        wtp[kp][m] = make_float2(W[(2 * kp) * N_SIMP + m0 + m],
                                 W[(2 * kp + 1) * N_SIMP + m0 + m]);
    }
    __syncthreads();

    ull acc[4][4];
    #pragma unroll
    for (int kp = 0; kp < 4; kp++)
        #pragma unroll
        for (int j = 0; j < 4; j++) acc[kp][j] = 0ULL;

    const float* Lp = L + (size_t)m0 * N_SIMP + c0;
    #pragma unroll 2
    for (int m = 0; m < ROWS1; m++) {
        float4 lv = *reinterpret_cast<const float4*>(Lp + (size_t)m * N_SIMP);
        ull ld[4] = { pack_dup(lv.x), pack_dup(lv.y), pack_dup(lv.z), pack_dup(lv.w) };
        #pragma unroll
        for (int kp = 0; kp < 4; kp++) {
            ull wp = *reinterpret_cast<const ull*>(&wtp[kp][m]);   // LDS.64 broadcast
            #pragma unroll
            for (int j = 0; j < 4; j++) fma2(acc[kp][j], ld[j], wp);
        }
    }

    // Write partials: per filter k, one float4 across the 4 columns.
    #pragma unroll
    for (int kp = 0; kp < 4; kp++) {
        float2 v0 = unpack2(acc[kp][0]);
        float2 v1 = unpack2(acc[kp][1]);
        float2 v2 = unpack2(acc[kp][2]);
        float2 v3 = unpack2(acc[kp][3]);
        float4 lo = make_float4(v0.x, v1.x, v2.x, v3.x);
        float4 hi = make_float4(v0.y, v1.y, v2.y, v3.y);
        *reinterpret_cast<float4*>(&g_wL_part[seg][2 * kp][c0])     = lo;
        *reinterpret_cast<float4*>(&g_wL_part[seg][2 * kp + 1][c0]) = hi;
    }
}

// ============================================================
// k1b: reduce 32 partial segments into g_wL. 65536 floats total.
// ============================================================
__global__ void k1_reduce() {
    int i = (blockIdx.x * 256 + threadIdx.x) * 4;   // 64 blocks * 256 thr * 4
    const float* base = &g_wL_part[0][0][0];
    float4 s = make_float4(0.f, 0.f, 0.f, 0.f);
    #pragma unroll
    for (int seg = 0; seg < SEG1; seg++) {
        float4 v = *reinterpret_cast<const float4*>(base + (size_t)seg * KF * N_SIMP + i);
        s.x += v.x; s.y += v.y; s.z += v.z; s.w += v.w;
    }
    *reinterpret_cast<float4*>(&g_wL[0][0] + i) = s;
}

// ============================================================
// k2: partial out accumulation. Block = (batch b, n segment).
// 128 threads = 32 f-groups (float4 over FEAT) x 4 n-subgroups.
// Each warp loads one full x row (512 B) per iteration — coalesced.
// ============================================================
__global__ __launch_bounds__(128) void k2_out(const float* __restrict__ x) {
    const int tid = threadIdx.x;
    const int fg  = tid & 31;
    const int ng  = tid >> 5;
    const int b   = blockIdx.x;
    const int seg = blockIdx.y;
    const int n0  = seg * ROWS2;

    __shared__ float2 wlp[4][ROWS2];   // 32 KB, k-pairs of wL for this segment
    for (int idx = tid; idx < 4 * ROWS2; idx += 128) {
        int kp = idx >> 10;
        int n  = idx & (ROWS2 - 1);
        wlp[kp][n] = make_float2(g_wL[2 * kp][n0 + n], g_wL[2 * kp + 1][n0 + n]);
    }
    __syncthreads();

    ull acc[4][4];
    #pragma unroll
    for (int kp = 0; kp < 4; kp++)
        #pragma unroll
        for (int j = 0; j < 4; j++) acc[kp][j] = 0ULL;

    const float* xb = x + ((size_t)b * N_SIMP + n0) * FEAT + fg * 4;
    #pragma unroll 2
    for (int n = ng; n < ROWS2; n += 4) {
        float4 xv = *reinterpret_cast<const float4*>(xb + (size_t)n * FEAT);
        ull xd[4] = { pack_dup(xv.x), pack_dup(xv.y), pack_dup(xv.z), pack_dup(xv.w) };
        #pragma unroll
        for (int kp = 0; kp < 4; kp++) {
            ull wp = *reinterpret_cast<const ull*>(&wlp[kp][n]);   // LDS.64 broadcast
            #pragma unroll
            for (int j = 0; j < 4; j++) fma2(acc[kp][j], xd[j], wp);
        }
    }

    const int part = seg * 4 + ng;
    #pragma unroll
    for (int kp = 0; kp < 4; kp++) {
        float2 v0 = unpack2(acc[kp][0]);
        float2 v1 = unpack2(acc[kp][1]);
        float2 v2 = unpack2(acc[kp][2]);
        float2 v3 = unpack2(acc[kp][3]);
        float4 lo = make_float4(v0.x, v1.x, v2.x, v3.x);
        float4 hi = make_float4(v0.y, v1.y, v2.y, v3.y);
        *reinterpret_cast<float4*>(&g_acc_part[part][2 * kp][b][fg * 4])     = lo;
        *reinterpret_cast<float4*>(&g_acc_part[part][2 * kp + 1][b][fg * 4]) = hi;
    }
}

// ============================================================
// k3: reduce 32 partials + tanh -> out [K, B, F] = 65536 floats.
// ============================================================
__global__ void k3_tanh(float* __restrict__ out) {
    int i = (blockIdx.x * 256 + threadIdx.x) * 4;   // 64 blocks * 256 thr * 4
    const float* base = &g_acc_part[0][0][0][0];
    float4 s = make_float4(0.f, 0.f, 0.f, 0.f);
    #pragma unroll
    for (int p = 0; p < PART2; p++) {
        float4 v = *reinterpret_cast<const float4*>(base + (size_t)p * KF * BATCH * FEAT + i);
        s.x += v.x; s.y += v.y; s.z += v.z; s.w += v.w;
    }
    float4 o = make_float4(tanhf(s.x), tanhf(s.y), tanhf(s.z), tanhf(s.w));
    *reinterpret_cast<float4*>(out + i) = o;
}

// ============================================================
extern "C" void kernel_launch(void* const* d_in, const int* in_sizes, int n_in,
                              void* d_out, int out_size) {
    const float* x = (const float*)d_in[0];   // [B, N, F]
    const float* L = (const float*)d_in[1];   // [N, N]
    const float* W = (const float*)d_in[2];   // [K, N]
    float* out = (float*)d_out;               // [K, B, F]

    k1_wl<<<dim3(COLB1, SEG1), 128>>>(W, L);
    k1_reduce<<<64, 256>>>();
    k2_out<<<dim3(BATCH, SEG2), 128>>>(x);
    k3_tanh<<<64, 256>>>(out);
}

// round 2
// speedup vs baseline: 1.2922x; 1.2922x over previous
#include <cuda_runtime.h>
#include <cstdint>
#include <cstddef>

#define N_SIMP 8192
#define KF 8
#define BATCH 64
#define FEAT 128

// ---- kernel 1 tiling: wL = W @ L ----
#define SEG1 32                    // row segments
#define ROWS1 (N_SIMP / SEG1)      // 256 rows per segment
#define COLB1 16                   // column blocks
#define COLS1 (N_SIMP / COLB1)     // 512 cols per block = 128 thr * 4

// ---- kernel 2 tiling: out = wL @ x[b] ----
#define SEG2 8                     // n segments
#define ROWS2 (N_SIMP / SEG2)      // 1024 n per segment
#define PART2 (SEG2 * 4)           // 32 partials (4 n-subgroups per block)

typedef unsigned long long ull;

// Scratch (device globals: allocation-free rule)
__device__ float g_wL_part[SEG1][KF][N_SIMP];          // 8 MB
__device__ float g_wL[KF][N_SIMP];                     // 256 KB
__device__ float g_acc_part[PART2][KF][BATCH][FEAT];   // 8 MB

__device__ __forceinline__ ull pack_dup(float a) {
    ull r; asm("mov.b64 %0, {%1, %1};" : "=l"(r) : "f"(a)); return r;
}
__device__ __forceinline__ void fma2(ull& d, ull a, ull b) {
    // packed f32x2 FMA: d = a*b + d on both halves (FFMA2 in SASS)
    asm("fma.rn.f32x2 %0, %1, %2, %0;" : "+l"(d) : "l"(a), "l"(b));
}
__device__ __forceinline__ float2 unpack2(ull v) {
    float2 r; asm("mov.b64 {%0, %1}, %2;" : "=f"(r.x), "=f"(r.y) : "l"(v)); return r;
}

// ============================================================
// k1: partial wL. Block = (col block, row segment).
// Thread owns 4 contiguous L columns, all 8 filters (4 k-pairs).
// MLP: 8 LDG.128 front-batched per chunk before any FMA.
// ============================================================
__global__ __launch_bounds__(128) void k1_wl(const float* __restrict__ W,
                                             const float* __restrict__ L) {
    const int tid  = threadIdx.x;
    const int colb = blockIdx.x;
    const int seg  = blockIdx.y;
    const int c0   = colb * COLS1 + tid * 4;
    const int m0   = seg * ROWS1;

    // W segment staged as k-pairs: wtp[kp][m] = {W[2kp][m0+m], W[2kp+1][m0+m]}
    __shared__ float2 wtp[4][ROWS1];   // 8 KB
    for (int idx = tid; idx < 4 * ROWS1; idx += 128) {
        int kp = idx / ROWS1;
        int m  = idx % ROWS1;
        wtp[kp][m] = make_float2(W[(2 * kp) * N_SIMP + m0 + m],
                                 W[(2 * kp + 1) * N_SIMP + m0 + m]);
    }
    __syncthreads();

    ull acc[4][4];
    #pragma unroll
    for (int kp = 0; kp < 4; kp++)
        #pragma unroll
        for (int j = 0; j < 4; j++) acc[kp][j] = 0ULL;

    const float* Lp = L + (size_t)m0 * N_SIMP + c0;
    for (int m = 0; m < ROWS1; m += 8) {
        // ---- front-batched loads: 8 independent LDG.128 in flight ----
        float4 lv[8];
        #pragma unroll
        for (int r = 0; r < 8; r++)
            lv[r] = __ldcs(reinterpret_cast<const float4*>(Lp + (size_t)(m + r) * N_SIMP));
        // ---- compute ----
        #pragma unroll
        for (int r = 0; r < 8; r++) {
            ull ld[4] = { pack_dup(lv[r].x), pack_dup(lv[r].y),
                          pack_dup(lv[r].z), pack_dup(lv[r].w) };
            #pragma unroll
            for (int kp = 0; kp < 4; kp++) {
                ull wp = *reinterpret_cast<const ull*>(&wtp[kp][m + r]);  // LDS.64 bcast
                #pragma unroll
                for (int j = 0; j < 4; j++) fma2(acc[kp][j], ld[j], wp);
            }
        }
    }

    #pragma unroll
    for (int kp = 0; kp < 4; kp++) {
        float2 v0 = unpack2(acc[kp][0]);
        float2 v1 = unpack2(acc[kp][1]);
        float2 v2 = unpack2(acc[kp][2]);
        float2 v3 = unpack2(acc[kp][3]);
        float4 lo = make_float4(v0.x, v1.x, v2.x, v3.x);
        float4 hi = make_float4(v0.y, v1.y, v2.y, v3.y);
        *reinterpret_cast<float4*>(&g_wL_part[seg][2 * kp][c0])     = lo;
        *reinterpret_cast<float4*>(&g_wL_part[seg][2 * kp + 1][c0]) = hi;
    }
}

// ============================================================
// k1b: reduce 32 partial segments into g_wL. 16384 float4 outputs.
// 8-deep load batches -> MLP 8.
// ============================================================
__global__ __launch_bounds__(128) void k1_reduce() {
    int i = (blockIdx.x * 128 + threadIdx.x) * 4;   // 128 blocks * 128 thr
    const float* base = &g_wL_part[0][0][0];
    float4 s = make_float4(0.f, 0.f, 0.f, 0.f);
    #pragma unroll
    for (int pb = 0; pb < SEG1; pb += 8) {
        float4 v[8];
        #pragma unroll
        for (int r = 0; r < 8; r++)
            v[r] = *reinterpret_cast<const float4*>(base + (size_t)(pb + r) * KF * N_SIMP + i);
        #pragma unroll
        for (int r = 0; r < 8; r++) {
            s.x += v[r].x; s.y += v[r].y; s.z += v[r].z; s.w += v[r].w;
        }
    }
    *reinterpret_cast<float4*>(&g_wL[0][0] + i) = s;
}

// ============================================================
// k2: partial out accumulation. Block = (batch b, n segment).
// 128 threads = 32 f-groups (float4 over FEAT) x 4 n-subgroups.
// Warp loads full x rows (512 B coalesced); 8 rows batched per chunk.
// ============================================================
__global__ __launch_bounds__(128) void k2_out(const float* __restrict__ x) {
    const int tid = threadIdx.x;
    const int fg  = tid & 31;
    const int ng  = tid >> 5;
    const int b   = blockIdx.x;
    const int seg = blockIdx.y;
    const int n0  = seg * ROWS2;

    __shared__ float2 wlp[4][ROWS2];   // 32 KB, k-pairs of wL for this segment
    for (int idx = tid; idx < 4 * ROWS2; idx += 128) {
        int kp = idx >> 10;
        int n  = idx & (ROWS2 - 1);
        wlp[kp][n] = make_float2(g_wL[2 * kp][n0 + n], g_wL[2 * kp + 1][n0 + n]);
    }
    __syncthreads();

    ull acc[4][4];
    #pragma unroll
    for (int kp = 0; kp < 4; kp++)
        #pragma unroll
        for (int j = 0; j < 4; j++) acc[kp][j] = 0ULL;

    // thread's rows: n = ng + 4*t; batch 8 of them per chunk (stride 32 rows)
    const float* xb = x + ((size_t)b * N_SIMP + n0) * FEAT + fg * 4;
    for (int nb = 0; nb < ROWS2; nb += 32) {
        float4 xv[8];
        #pragma unroll
        for (int r = 0; r < 8; r++)
            xv[r] = __ldcs(reinterpret_cast<const float4*>(
                        xb + (size_t)(nb + ng + 4 * r) * FEAT));
        #pragma unroll
        for (int r = 0; r < 8; r++) {
            int n = nb + ng + 4 * r;
            ull xd[4] = { pack_dup(xv[r].x), pack_dup(xv[r].y),
                          pack_dup(xv[r].z), pack_dup(xv[r].w) };
            #pragma unroll
            for (int kp = 0; kp < 4; kp++) {
                ull wp = *reinterpret_cast<const ull*>(&wlp[kp][n]);   // LDS.64 bcast
                #pragma unroll
                for (int j = 0; j < 4; j++) fma2(acc[kp][j], xd[j], wp);
            }
        }
    }

    const int part = seg * 4 + ng;
    #pragma unroll
    for (int kp = 0; kp < 4; kp++) {
        float2 v0 = unpack2(acc[kp][0]);
        float2 v1 = unpack2(acc[kp][1]);
        float2 v2 = unpack2(acc[kp][2]);
        float2 v3 = unpack2(acc[kp][3]);
        float4 lo = make_float4(v0.x, v1.x, v2.x, v3.x);
        float4 hi = make_float4(v0.y, v1.y, v2.y, v3.y);
        *reinterpret_cast<float4*>(&g_acc_part[part][2 * kp][b][fg * 4])     = lo;
        *reinterpret_cast<float4*>(&g_acc_part[part][2 * kp + 1][b][fg * 4]) = hi;
    }
}

// ============================================================
// k3: reduce 32 partials + tanh -> out [K, B, F]. 16384 float4 outputs.
// 8-deep load batches -> MLP 8.
// ============================================================
__global__ __launch_bounds__(128) void k3_tanh(float* __restrict__ out) {
    int i = (blockIdx.x * 128 + threadIdx.x) * 4;   // 128 blocks * 128 thr
    const float* base = &g_acc_part[0][0][0][0];
    float4 s = make_float4(0.f, 0.f, 0.f, 0.f);
    #pragma unroll
    for (int pb = 0; pb < PART2; pb += 8) {
        float4 v[8];
        #pragma unroll
        for (int r = 0; r < 8; r++)
            v[r] = *reinterpret_cast<const float4*>(
                       base + (size_t)(pb + r) * KF * BATCH * FEAT + i);
        #pragma unroll
        for (int r = 0; r < 8; r++) {
            s.x += v[r].x; s.y += v[r].y; s.z += v[r].z; s.w += v[r].w;
        }
    }
    float4 o = make_float4(tanhf(s.x), tanhf(s.y), tanhf(s.z), tanhf(s.w));
    *reinterpret_cast<float4*>(out + i) = o;
}

// ============================================================
extern "C" void kernel_launch(void* const* d_in, const int* in_sizes, int n_in,
                              void* d_out, int out_size) {
    const float* x = (const float*)d_in[0];   // [B, N, F]
    const float* L = (const float*)d_in[1];   // [N, N]
    const float* W = (const float*)d_in[2];   // [K, N]
    float* out = (float*)d_out;               // [K, B, F]

    k1_wl<<<dim3(COLB1, SEG1), 128>>>(W, L);
    k1_reduce<<<128, 128>>>();
    k2_out<<<dim3(BATCH, SEG2), 128>>>(x);
    k3_tanh<<<128, 128>>>(out);
}

// round 4
// speedup vs baseline: 1.6312x; 1.2623x over previous
#include <cuda_runtime.h>
#include <cstdint>
#include <cstddef>

#define N_SIMP 8192
#define KF 8
#define BATCH 64
#define FEAT 128

// ---- kernel 1 tiling: wL = W @ L ----
#define SEG1 32                    // row segments
#define ROWS1 (N_SIMP / SEG1)      // 256 rows per segment
#define COLB1 16                   // column blocks
#define COLS1 (N_SIMP / COLB1)     // 512 cols per block = 128 thr * 4

// ---- kernel 2 tiling: out = wL @ x[b] ----
#define SEG2 8                     // n segments
#define ROWS2 (N_SIMP / SEG2)      // 1024 n per segment
#define PART2 (SEG2 * 4)           // 32 partials (4 n-subgroups per block)

typedef unsigned long long ull;

// Scratch (device globals: allocation-free rule)
__device__ float g_wL_part[SEG1][KF][N_SIMP];          // 8 MB
__device__ float g_wL[KF][N_SIMP];                     // 256 KB
__device__ float g_acc_part[PART2][KF][BATCH][FEAT];   // 8 MB

__device__ __forceinline__ ull pack_dup(float a) {
    ull r; asm("mov.b64 %0, {%1, %1};" : "=l"(r) : "f"(a)); return r;
}
__device__ __forceinline__ void fma2(ull& d, ull a, ull b) {
    // packed f32x2 FMA: d = a*b + d on both halves (FFMA2 in SASS)
    asm("fma.rn.f32x2 %0, %1, %2, %0;" : "+l"(d) : "l"(a), "l"(b));
}
__device__ __forceinline__ float2 unpack2(ull v) {
    float2 r; asm("mov.b64 {%0, %1}, %2;" : "=f"(r.x), "=f"(r.y) : "l"(v)); return r;
}

// ============================================================
// k1: partial wL. Block = (col block, row segment).
// Thread owns 4 contiguous L columns, all 8 filters (4 k-pairs).
// Double-buffered 8-row blocks: next block's LDGs issue before
// current block's FMAs -> sustained MLP ~8.
// ============================================================
__device__ __forceinline__ void k1_compute8(const float4* lv, int mbase,
                                            ull acc[4][4],
                                            const float2 wtp[4][ROWS1]) {
    #pragma unroll
    for (int r = 0; r < 8; r++) {
        ull ld[4] = { pack_dup(lv[r].x), pack_dup(lv[r].y),
                      pack_dup(lv[r].z), pack_dup(lv[r].w) };
        #pragma unroll
        for (int kp = 0; kp < 4; kp++) {
            ull wp = *reinterpret_cast<const ull*>(&wtp[kp][mbase + r]);  // LDS.64 bcast
            #pragma unroll
            for (int j = 0; j < 4; j++) fma2(acc[kp][j], ld[j], wp);
        }
    }
}

__global__ __launch_bounds__(128, 1) void k1_wl(const float* __restrict__ W,
                                                const float* __restrict__ L) {
    const int tid  = threadIdx.x;
    const int colb = blockIdx.x;
    const int seg  = blockIdx.y;
    const int c0   = colb * COLS1 + tid * 4;
    const int m0   = seg * ROWS1;

    __shared__ float2 wtp[4][ROWS1];   // 8 KB, W segment as k-pairs
    for (int idx = tid; idx < 4 * ROWS1; idx += 128) {
        int kp = idx / ROWS1;
        int m  = idx % ROWS1;
        wtp[kp][m] = make_float2(W[(2 * kp) * N_SIMP + m0 + m],
                                 W[(2 * kp + 1) * N_SIMP + m0 + m]);
    }
    __syncthreads();

    ull acc[4][4];
    #pragma unroll
    for (int kp = 0; kp < 4; kp++)
        #pragma unroll
        for (int j = 0; j < 4; j++) acc[kp][j] = 0ULL;

    const float* Lp = L + (size_t)m0 * N_SIMP + c0;

    float4 bufA[8], bufB[8];
    #pragma unroll
    for (int r = 0; r < 8; r++)
        bufA[r] = __ldcs(reinterpret_cast<const float4*>(Lp + (size_t)r * N_SIMP));

    for (int m = 0; m < ROWS1; m += 16) {
        #pragma unroll
        for (int r = 0; r < 8; r++)
            bufB[r] = __ldcs(reinterpret_cast<const float4*>(
                          Lp + (size_t)(m + 8 + r) * N_SIMP));
        k1_compute8(bufA, m, acc, wtp);
        if (m + 16 < ROWS1) {
            #pragma unroll
            for (int r = 0; r < 8; r++)
                bufA[r] = __ldcs(reinterpret_cast<const float4*>(
                              Lp + (size_t)(m + 16 + r) * N_SIMP));
        }
        k1_compute8(bufB, m + 8, acc, wtp);
    }

    #pragma unroll
    for (int kp = 0; kp < 4; kp++) {
        float2 v0 = unpack2(acc[kp][0]);
        float2 v1 = unpack2(acc[kp][1]);
        float2 v2 = unpack2(acc[kp][2]);
        float2 v3 = unpack2(acc[kp][3]);
        float4 lo = make_float4(v0.x, v1.x, v2.x, v3.x);
        float4 hi = make_float4(v0.y, v1.y, v2.y, v3.y);
        *reinterpret_cast<float4*>(&g_wL_part[seg][2 * kp][c0])     = lo;
        *reinterpret_cast<float4*>(&g_wL_part[seg][2 * kp + 1][c0]) = hi;
    }
}

// ============================================================
// k1b: reduce 32 partial segments into g_wL.
// float2 granularity: 32768 threads (grid 256 x 128), 8-deep batches.
// Data batch = 16 regs -> MLP 8 survives any reg budget.
// ============================================================
__global__ __launch_bounds__(128, 1) void k1_reduce() {
    int i = blockIdx.x * 128 + threadIdx.x;           // float2 index, 32768 total
    const float2* base = reinterpret_cast<const float2*>(&g_wL_part[0][0][0]);
    const int seg_stride = KF * N_SIMP / 2;           // 32768 float2 per segment
    float2 s = make_float2(0.f, 0.f);
    #pragma unroll
    for (int pb = 0; pb < SEG1; pb += 8) {
        float2 v[8];
        #pragma unroll
        for (int r = 0; r < 8; r++)
            v[r] = base[(size_t)(pb + r) * seg_stride + i];
        #pragma unroll
        for (int r = 0; r < 8; r++) { s.x += v[r].x; s.y += v[r].y; }
    }
    reinterpret_cast<float2*>(&g_wL[0][0])[i] = s;
}

// ============================================================
// k2: partial out accumulation. Block = (batch b, n segment).
// 128 threads = 32 f-groups (float4 over FEAT) x 4 n-subgroups.
// Double-buffered 8-row blocks (stride 32 rows) -> sustained MLP ~8.
// ============================================================
__device__ __forceinline__ void k2_compute8(const float4* xv, int nb, int ng,
                                            ull acc[4][4],
                                            const float2 wlp[4][ROWS2]) {
    #pragma unroll
    for (int r = 0; r < 8; r++) {
        int n = nb + ng + 4 * r;
        ull xd[4] = { pack_dup(xv[r].x), pack_dup(xv[r].y),
                      pack_dup(xv[r].z), pack_dup(xv[r].w) };
        #pragma unroll
        for (int kp = 0; kp < 4; kp++) {
            ull wp = *reinterpret_cast<const ull*>(&wlp[kp][n]);   // LDS.64 bcast
            #pragma unroll
            for (int j = 0; j < 4; j++) fma2(acc[kp][j], xd[j], wp);
        }
    }
}

__global__ __launch_bounds__(128, 1) void k2_out(const float* __restrict__ x) {
    const int tid = threadIdx.x;
    const int fg  = tid & 31;
    const int ng  = tid >> 5;
    const int b   = blockIdx.x;
    const int seg = blockIdx.y;
    const int n0  = seg * ROWS2;

    __shared__ float2 wlp[4][ROWS2];   // 32 KB, k-pairs of wL for this segment
    for (int idx = tid; idx < 4 * ROWS2; idx += 128) {
        int kp = idx >> 10;
        int n  = idx & (ROWS2 - 1);
        wlp[kp][n] = make_float2(g_wL[2 * kp][n0 + n], g_wL[2 * kp + 1][n0 + n]);
    }
    __syncthreads();

    ull acc[4][4];
    #pragma unroll
    for (int kp = 0; kp < 4; kp++)
        #pragma unroll
        for (int j = 0; j < 4; j++) acc[kp][j] = 0ULL;

    const float* xb = x + ((size_t)b * N_SIMP + n0) * FEAT + fg * 4;

    float4 bufA[8], bufB[8];
    #pragma unroll
    for (int r = 0; r < 8; r++)
        bufA[r] = __ldcs(reinterpret_cast<const float4*>(
                      xb + (size_t)(ng + 4 * r) * FEAT));

    for (int nb = 0; nb < ROWS2; nb += 64) {
        #pragma unroll
        for (int r = 0; r < 8; r++)
            bufB[r] = __ldcs(reinterpret_cast<const float4*>(
                          xb + (size_t)(nb + 32 + ng + 4 * r) * FEAT));
        k2_compute8(bufA, nb, ng, acc, wlp);
        if (nb + 64 < ROWS2) {
            #pragma unroll
            for (int r = 0; r < 8; r++)
                bufA[r] = __ldcs(reinterpret_cast<const float4*>(
                              xb + (size_t)(nb + 64 + ng + 4 * r) * FEAT));
        }
        k2_compute8(bufB, nb + 32, ng, acc, wlp);
    }

    const int part = seg * 4 + ng;
    #pragma unroll
    for (int kp = 0; kp < 4; kp++) {
        float2 v0 = unpack2(acc[kp][0]);
        float2 v1 = unpack2(acc[kp][1]);
        float2 v2 = unpack2(acc[kp][2]);
        float2 v3 = unpack2(acc[kp][3]);
        float4 lo = make_float4(v0.x, v1.x, v2.x, v3.x);
        float4 hi = make_float4(v0.y, v1.y, v2.y, v3.y);
        *reinterpret_cast<float4*>(&g_acc_part[part][2 * kp][b][fg * 4])     = lo;
        *reinterpret_cast<float4*>(&g_acc_part[part][2 * kp + 1][b][fg * 4]) = hi;
    }
}

// ============================================================
// k3: reduce 32 partials + tanh -> out [K, B, F].
// float2 granularity: 32768 threads (grid 256 x 128), 8-deep batches.
// ============================================================
__global__ __launch_bounds__(128, 1) void k3_tanh(float* __restrict__ out) {
    int i = blockIdx.x * 128 + threadIdx.x;           // float2 index, 32768 total
    const float2* base = reinterpret_cast<const float2*>(&g_acc_part[0][0][0][0]);
    const int part_stride = KF * BATCH * FEAT / 2;    // 32768 float2 per partial
    float2 s = make_float2(0.f, 0.f);
    #pragma unroll
    for (int pb = 0; pb < PART2; pb += 8) {
        float2 v[8];
        #pragma unroll
        for (int r = 0; r < 8; r++)
            v[r] = base[(size_t)(pb + r) * part_stride + i];
        #pragma unroll
        for (int r = 0; r < 8; r++) { s.x += v[r].x; s.y += v[r].y; }
    }
    reinterpret_cast<float2*>(out)[i] = make_float2(tanhf(s.x), tanhf(s.y));
}

// ============================================================
extern "C" void kernel_launch(void* const* d_in, const int* in_sizes, int n_in,
                              void* d_out, int out_size) {
    const float* x = (const float*)d_in[0];   // [B, N, F]
    const float* L = (const float*)d_in[1];   // [N, N]
    const float* W = (const float*)d_in[2];   // [K, N]
    float* out = (float*)d_out;               // [K, B, F]

    k1_wl<<<dim3(COLB1, SEG1), 128>>>(W, L);
    k1_reduce<<<256, 128>>>();
    k2_out<<<dim3(BATCH, SEG2), 128>>>(x);
    k3_tanh<<<256, 128>>>(out);
}

// round 5
// speedup vs baseline: 1.6914x; 1.0369x over previous
#include <cuda_runtime.h>
#include <cstdint>
#include <cstddef>

#define N_SIMP 8192
#define KF 8
#define BATCH 64
#define FEAT 128

// ---- kernel 1 tiling: wL = W @ L ----
#define SEG1 16                    // row segments (partial slices)
#define ROWS1 (N_SIMP / SEG1)      // 512 rows per segment
#define COLB1 16                   // column blocks
#define COLS1 (N_SIMP / COLB1)     // 512 cols per block = 128 thr * 4

// ---- kernel 2 tiling: out = wL @ x[b] ----
#define SEG2 8                     // n segments
#define ROWS2 (N_SIMP / SEG2)      // 1024 n per segment

typedef unsigned long long ull;

// Scratch (device globals: allocation-free rule)
__device__ float g_wL_part[SEG1][KF][N_SIMP];          // 4 MB
__device__ float g_wL[KF][N_SIMP];                     // 256 KB
__device__ float g_acc_part[SEG2][KF][BATCH][FEAT];    // 2 MB

__device__ __forceinline__ ull pack_dup(float a) {
    ull r; asm("mov.b64 %0, {%1, %1};" : "=l"(r) : "f"(a)); return r;
}
__device__ __forceinline__ void fma2(ull& d, ull a, ull b) {
    // packed f32x2 FMA: d = a*b + d on both halves (FFMA2 in SASS)
    asm("fma.rn.f32x2 %0, %1, %2, %0;" : "+l"(d) : "l"(a), "l"(b));
}
__device__ __forceinline__ float2 unpack2(ull v) {
    float2 r; asm("mov.b64 {%0, %1}, %2;" : "=f"(r.x), "=f"(r.y) : "l"(v)); return r;
}

// ============================================================
// k1: partial wL. Block = (col block, row segment). 256 CTAs.
// Thread owns 4 contiguous L columns, all 8 filters (4 k-pairs).
// Double-buffered 8-row blocks -> sustained MLP ~8.
// ============================================================
__device__ __forceinline__ void k1_compute8(const float4* lv, int mbase,
                                            ull acc[4][4],
                                            const float2 wtp[4][ROWS1]) {
    #pragma unroll
    for (int r = 0; r < 8; r++) {
        ull ld[4] = { pack_dup(lv[r].x), pack_dup(lv[r].y),
                      pack_dup(lv[r].z), pack_dup(lv[r].w) };
        #pragma unroll
        for (int kp = 0; kp < 4; kp++) {
            ull wp = *reinterpret_cast<const ull*>(&wtp[kp][mbase + r]);  // LDS.64 bcast
            #pragma unroll
            for (int j = 0; j < 4; j++) fma2(acc[kp][j], ld[j], wp);
        }
    }
}

__global__ __launch_bounds__(128, 1) void k1_wl(const float* __restrict__ W,
                                                const float* __restrict__ L) {
    const int tid  = threadIdx.x;
    const int colb = blockIdx.x;
    const int seg  = blockIdx.y;
    const int c0   = colb * COLS1 + tid * 4;
    const int m0   = seg * ROWS1;

    __shared__ float2 wtp[4][ROWS1];   // 16 KB, W segment as k-pairs
    for (int idx = tid; idx < 4 * ROWS1; idx += 128) {
        int kp = idx / ROWS1;
        int m  = idx % ROWS1;
        wtp[kp][m] = make_float2(W[(2 * kp) * N_SIMP + m0 + m],
                                 W[(2 * kp + 1) * N_SIMP + m0 + m]);
    }
    __syncthreads();

    ull acc[4][4];
    #pragma unroll
    for (int kp = 0; kp < 4; kp++)
        #pragma unroll
        for (int j = 0; j < 4; j++) acc[kp][j] = 0ULL;

    const float* Lp = L + (size_t)m0 * N_SIMP + c0;

    float4 bufA[8], bufB[8];
    #pragma unroll
    for (int r = 0; r < 8; r++)
        bufA[r] = __ldcs(reinterpret_cast<const float4*>(Lp + (size_t)r * N_SIMP));

    for (int m = 0; m < ROWS1; m += 16) {
        #pragma unroll
        for (int r = 0; r < 8; r++)
            bufB[r] = __ldcs(reinterpret_cast<const float4*>(
                          Lp + (size_t)(m + 8 + r) * N_SIMP));
        k1_compute8(bufA, m, acc, wtp);
        if (m + 16 < ROWS1) {
            #pragma unroll
            for (int r = 0; r < 8; r++)
                bufA[r] = __ldcs(reinterpret_cast<const float4*>(
                              Lp + (size_t)(m + 16 + r) * N_SIMP));
        }
        k1_compute8(bufB, m + 8, acc, wtp);
    }

    #pragma unroll
    for (int kp = 0; kp < 4; kp++) {
        float2 v0 = unpack2(acc[kp][0]);
        float2 v1 = unpack2(acc[kp][1]);
        float2 v2 = unpack2(acc[kp][2]);
        float2 v3 = unpack2(acc[kp][3]);
        float4 lo = make_float4(v0.x, v1.x, v2.x, v3.x);
        float4 hi = make_float4(v0.y, v1.y, v2.y, v3.y);
        __stcs(reinterpret_cast<float4*>(&g_wL_part[seg][2 * kp][c0]),     lo);
        __stcs(reinterpret_cast<float4*>(&g_wL_part[seg][2 * kp + 1][c0]), hi);
    }
}

// ============================================================
// k1b: reduce 16 partial segments into g_wL.
// float2 granularity: 32768 threads, 8-deep load batches.
// ============================================================
__global__ __launch_bounds__(128, 1) void k1_reduce() {
    int i = blockIdx.x * 128 + threadIdx.x;           // float2 index, 32768 total
    const float2* base = reinterpret_cast<const float2*>(&g_wL_part[0][0][0]);
    const int seg_stride = KF * N_SIMP / 2;           // 32768 float2 per segment
    float2 s = make_float2(0.f, 0.f);
    #pragma unroll
    for (int pb = 0; pb < SEG1; pb += 8) {
        float2 v[8];
        #pragma unroll
        for (int r = 0; r < 8; r++)
            v[r] = __ldcs(&base[(size_t)(pb + r) * seg_stride + i]);
        #pragma unroll
        for (int r = 0; r < 8; r++) { s.x += v[r].x; s.y += v[r].y; }
    }
    reinterpret_cast<float2*>(&g_wL[0][0])[i] = s;
}

// ============================================================
// k2: partial out accumulation. Block = (batch b, n segment).
// 128 threads = 32 f-groups (float4 over FEAT) x 4 n-subgroups.
// Double-buffered 8-row blocks (stride 32 rows) -> sustained MLP ~8.
// Epilogue: tree-reduce the 4 n-subgroups via smem -> one slice per CTA.
// ============================================================
__device__ __forceinline__ void k2_compute8(const float4* xv, int nb, int ng,
                                            ull acc[4][4],
                                            const float2 wlp[4][ROWS2]) {
    #pragma unroll
    for (int r = 0; r < 8; r++) {
        int n = nb + ng + 4 * r;
        ull xd[4] = { pack_dup(xv[r].x), pack_dup(xv[r].y),
                      pack_dup(xv[r].z), pack_dup(xv[r].w) };
        #pragma unroll
        for (int kp = 0; kp < 4; kp++) {
            ull wp = *reinterpret_cast<const ull*>(&wlp[kp][n]);   // LDS.64 bcast
            #pragma unroll
            for (int j = 0; j < 4; j++) fma2(acc[kp][j], xd[j], wp);
        }
    }
}

__global__ __launch_bounds__(128, 1) void k2_out(const float* __restrict__ x) {
    const int tid = threadIdx.x;
    const int fg  = tid & 31;
    const int ng  = tid >> 5;
    const int b   = blockIdx.x;
    const int seg = blockIdx.y;
    const int n0  = seg * ROWS2;

    __shared__ float2 wlp[4][ROWS2];   // 32 KB, k-pairs of wL for this segment
    for (int idx = tid; idx < 4 * ROWS2; idx += 128) {
        int kp = idx >> 10;
        int n  = idx & (ROWS2 - 1);
        wlp[kp][n] = make_float2(g_wL[2 * kp][n0 + n], g_wL[2 * kp + 1][n0 + n]);
    }
    __syncthreads();

    ull acc[4][4];
    #pragma unroll
    for (int kp = 0; kp < 4; kp++)
        #pragma unroll
        for (int j = 0; j < 4; j++) acc[kp][j] = 0ULL;

    const float* xb = x + ((size_t)b * N_SIMP + n0) * FEAT + fg * 4;

    float4 bufA[8], bufB[8];
    #pragma unroll
    for (int r = 0; r < 8; r++)
        bufA[r] = __ldcs(reinterpret_cast<const float4*>(
                      xb + (size_t)(ng + 4 * r) * FEAT));

    for (int nb = 0; nb < ROWS2; nb += 64) {
        #pragma unroll
        for (int r = 0; r < 8; r++)
            bufB[r] = __ldcs(reinterpret_cast<const float4*>(
                          xb + (size_t)(nb + 32 + ng + 4 * r) * FEAT));
        k2_compute8(bufA, nb, ng, acc, wlp);
        if (nb + 64 < ROWS2) {
            #pragma unroll
            for (int r = 0; r < 8; r++)
                bufA[r] = __ldcs(reinterpret_cast<const float4*>(
                              xb + (size_t)(nb + 64 + ng + 4 * r) * FEAT));
        }
        k2_compute8(bufB, nb + 32, ng, acc, wlp);
    }

    // ---- epilogue: reduce over the 4 n-subgroups via smem (2 rounds) ----
    // Per-thread partial = 32 floats (8 k x 4 f). Buffer: 2 src-groups x
    // 32 fg-threads x 32 floats = 8 KB, overlaid on wlp (done with it).
    __syncthreads();
    float (*rbuf)[32][32] = reinterpret_cast<float (*)[32][32]>(&wlp[0][0]);

    float mine[32];
    #pragma unroll
    for (int kp = 0; kp < 4; kp++) {
        #pragma unroll
        for (int j = 0; j < 4; j++) {
            float2 v = unpack2(acc[kp][j]);
            mine[(2 * kp) * 4 + j]     = v.x;
            mine[(2 * kp + 1) * 4 + j] = v.y;
        }
    }

    // round 1: ng 2,3 -> buffer; ng 0,1 accumulate
    if (ng >= 2) {
        #pragma unroll
        for (int t = 0; t < 32; t++) rbuf[ng - 2][fg][t] = mine[t];
    }
    __syncthreads();
    if (ng < 2) {
        #pragma unroll
        for (int t = 0; t < 32; t++) mine[t] += rbuf[ng][fg][t];
    }
    __syncthreads();
    // round 2: ng 1 -> buffer; ng 0 accumulates and stores
    if (ng == 1) {
        #pragma unroll
        for (int t = 0; t < 32; t++) rbuf[0][fg][t] = mine[t];
    }
    __syncthreads();
    if (ng == 0) {
        #pragma unroll
        for (int k = 0; k < 8; k++) {
            float4 o = make_float4(mine[k * 4 + 0] + rbuf[0][fg][k * 4 + 0],
                                   mine[k * 4 + 1] + rbuf[0][fg][k * 4 + 1],
                                   mine[k * 4 + 2] + rbuf[0][fg][k * 4 + 2],
                                   mine[k * 4 + 3] + rbuf[0][fg][k * 4 + 3]);
            __stcs(reinterpret_cast<float4*>(&g_acc_part[seg][k][b][fg * 4]), o);
        }
    }
}

// ============================================================
// k3: reduce 8 partials + tanh -> out [K, B, F]. 32768 float2 threads.
// ============================================================
__global__ __launch_bounds__(128, 1) void k3_tanh(float* __restrict__ out) {
    int i = blockIdx.x * 128 + threadIdx.x;           // float2 index, 32768 total
    const float2* base = reinterpret_cast<const float2*>(&g_acc_part[0][0][0][0]);
    const int part_stride = KF * BATCH * FEAT / 2;    // 32768 float2 per partial
    float2 v[SEG2];
    #pragma unroll
    for (int r = 0; r < SEG2; r++)
        v[r] = __ldcs(&base[(size_t)r * part_stride + i]);
    float2 s = make_float2(0.f, 0.f);
    #pragma unroll
    for (int r = 0; r < SEG2; r++) { s.x += v[r].x; s.y += v[r].y; }
    reinterpret_cast<float2*>(out)[i] = make_float2(tanhf(s.x), tanhf(s.y));
}

// ============================================================
extern "C" void kernel_launch(void* const* d_in, const int* in_sizes, int n_in,
                              void* d_out, int out_size) {
    const float* x = (const float*)d_in[0];   // [B, N, F]
    const float* L = (const float*)d_in[1];   // [N, N]
    const float* W = (const float*)d_in[2];   // [K, N]
    float* out = (float*)d_out;               // [K, B, F]

    k1_wl<<<dim3(COLB1, SEG1), 128>>>(W, L);
    k1_reduce<<<256, 128>>>();
    k2_out<<<dim3(BATCH, SEG2), 128>>>(x);
    k3_tanh<<<256, 128>>>(out);
}